// round 2
// baseline (speedup 1.0000x reference)
#include <cuda_runtime.h>
#include <math.h>

#define HW 16384

// ------------------------- scratch (static device globals) -------------------------
__device__ float g_t1[(size_t)4*64*HW];      // te1 out
__device__ float g_tex[(size_t)4*128*HW];    // te2 out (tex)
__device__ float g_g1b[(size_t)4*64*HW];     // g1 out
__device__ float g_f1o[(size_t)4*256*HW];    // f1 out
__device__ float g_wbuf[(size_t)4*1176*HW];  // f2 out -> softmax'd weights [b][c][49][hw]
__device__ float g_latA[(size_t)4*24*HW];
__device__ float g_latB[(size_t)4*24*HW];
__device__ float g_intens[(size_t)4*HW];     // intensity map
__device__ float g_S[4*256*9];               // emb tap sums for f1

// ------------------------- te1: 3->64 conv3x3 + relu -------------------------
__global__ __launch_bounds__(128) void te1_kernel(const float* __restrict__ in,
    const float* __restrict__ w, const float* __restrict__ bias) {
  int y = blockIdx.x, b = blockIdx.y, x = threadIdx.x;
  __shared__ float Ws[64*27];
  __shared__ float bsh[64];
  for (int i = threadIdx.x; i < 64*27; i += 128) Ws[i] = w[i];
  if (threadIdx.x < 64) bsh[threadIdx.x] = bias[threadIdx.x];
  __syncthreads();
  float iv[27];
  #pragma unroll
  for (int c = 0; c < 3; c++)
    #pragma unroll
    for (int ki = 0; ki < 3; ki++)
      #pragma unroll
      for (int kj = 0; kj < 3; kj++) {
        int gy = y + ki - 1, gx = x + kj - 1;
        iv[c*9+ki*3+kj] = ((unsigned)gy < 128u && (unsigned)gx < 128u)
            ? in[((b*3+c)*128+gy)*128+gx] : 0.f;
      }
  for (int oc = 0; oc < 64; oc++) {
    float s = bsh[oc];
    #pragma unroll
    for (int k = 0; k < 27; k++) s += Ws[oc*27+k] * iv[k];
    g_t1[(((size_t)b*64+oc)*128+y)*128+x] = fmaxf(s, 0.f);
  }
}

// ------------------------- generic conv3x3 (zero pad), register-tiled -------------------------
// Block: BM output channels x 128 pixels (one full row). 256 threads, thread tile (BM/16)x8.
// EMB: add per-(b,oc,tap) constant S over valid taps (class-embedding half of f1's input).
template<int CIN, int BM, bool RELU, bool EMB>
__global__ __launch_bounds__(256) void conv3x3_kernel(
    const float* __restrict__ in, const float* __restrict__ w,
    const float* __restrict__ bias, float* __restrict__ out,
    int cout, int wstride) {
  constexpr int IT = BM/16;
  const int y = blockIdx.x;
  const int ocb = blockIdx.y * BM;
  const int b = blockIdx.z;
  const int tid = threadIdx.x, tx = tid & 15, ty = tid >> 4;

  __shared__ float Ws[BM][4][9];
  __shared__ float Bs[4][3][132];
  __shared__ float Ss[BM][9];

  if (EMB) {
    for (int i = tid; i < BM*9; i += 256) {
      int oc = i/9;
      Ss[oc][i%9] = g_S[(b*256 + ocb + oc)*9 + i%9];
    }
  }

  float acc[IT][8];
  #pragma unroll
  for (int i = 0; i < IT; i++)
    #pragma unroll
    for (int j = 0; j < 8; j++) acc[i][j] = 0.f;

  const float* inB = in + (size_t)b*CIN*HW;

  for (int ic0 = 0; ic0 < CIN; ic0 += 4) {
    // weights tile [BM][4 ic][9 taps]
    for (int idx = tid; idx < BM*36; idx += 256) {
      int oc = idx/36, r = idx%36, ic = r/9, tap = r%9;
      float v = 0.f;
      if (ocb + oc < cout)
        v = w[(size_t)(ocb+oc)*wstride + (ic0+ic)*9 + tap];
      Ws[oc][ic][tap] = v;
    }
    // input rows y-1..y+1, cols -1..128 (halo), zero pad
    for (int idx = tid; idx < 4*3*130; idx += 256) {
      int ic = idx/390, r = idx%390, ki = r/130, col = r%130;
      int gy = y + ki - 1, gx = col - 1;
      float v = 0.f;
      if ((unsigned)gy < 128u && (unsigned)gx < 128u)
        v = inB[(size_t)(ic0+ic)*HW + gy*128 + gx];
      Bs[ic][ki][col] = v;
    }
    __syncthreads();
    #pragma unroll
    for (int ic = 0; ic < 4; ic++) {
      #pragma unroll
      for (int ki = 0; ki < 3; ki++) {
        #pragma unroll
        for (int kj = 0; kj < 3; kj++) {
          float a[IT];
          #pragma unroll
          for (int i = 0; i < IT; i++) a[i] = Ws[ty + i*16][ic][ki*3+kj];
          #pragma unroll
          for (int j = 0; j < 8; j++) {
            float bv = Bs[ic][ki][j*16 + tx + kj];
            #pragma unroll
            for (int i = 0; i < IT; i++) acc[i][j] += a[i]*bv;
          }
        }
      }
    }
    __syncthreads();
  }
  #pragma unroll
  for (int i = 0; i < IT; i++) {
    int oc = ocb + ty + i*16;
    if (oc >= cout) continue;
    float bs = bias[oc];
    float* op = out + (((size_t)b*cout + oc)*128 + y)*128;
    #pragma unroll
    for (int j = 0; j < 8; j++) {
      int x = j*16 + tx;
      float v = acc[i][j] + bs;
      if (EMB) {
        #pragma unroll
        for (int ki = 0; ki < 3; ki++) {
          int gy = y + ki - 1;
          if ((unsigned)gy >= 128u) continue;
          #pragma unroll
          for (int kj = 0; kj < 3; kj++) {
            int gx = x + kj - 1;
            if ((unsigned)gx >= 128u) continue;
            v += Ss[ty + i*16][ki*3+kj];
          }
        }
      }
      if (RELU) v = fmaxf(v, 0.f);
      op[x] = v;
    }
  }
}

// ------------------------- emb tap sums: S[b][o][tap] = sum_c w_f1[o,128+c,tap]*emb[label_b,c]
__global__ void embS_kernel(const float* __restrict__ wf1,
    const float* __restrict__ emb, const int* __restrict__ labels) {
  int idx = blockIdx.x*256 + threadIdx.x;
  if (idx >= 4*256*9) return;
  int b = idx/(256*9); int r = idx - b*2304; int o = r/9; int tap = r - o*9;
  int l = labels[b];
  float s = 0.f;
  for (int c = 0; c < 128; c++)
    s += wf1[(size_t)o*2304 + (128+c)*9 + tap] * emb[l*128+c];
  g_S[idx] = s;
}

// ------------------------- gate: 1x1 conv 64->6 + sigmoid; writes class_gate/cond/intensity
__global__ __launch_bounds__(256) void gate_kernel(const float* __restrict__ wg2,
    const float* __restrict__ bg2, const int* __restrict__ labels,
    const float* __restrict__ ci, float* __restrict__ out_cg,
    float* __restrict__ out_cond) {
  int p = blockIdx.x*256 + threadIdx.x;
  int b = blockIdx.y;
  __shared__ float Ws[6*64];
  for (int i = threadIdx.x; i < 384; i += 256) Ws[i] = wg2[i];
  __syncthreads();
  float s[6];
  #pragma unroll
  for (int k = 0; k < 6; k++) s[k] = bg2[k];
  const float* gp = g_g1b + (size_t)b*64*HW + p;
  #pragma unroll
  for (int c = 0; c < 64; c++) {
    float v = gp[(size_t)c*HW];
    #pragma unroll
    for (int k = 0; k < 6; k++) s[k] += Ws[k*64+c]*v;
  }
  int l = labels[b];
  float gl = 0.f;
  #pragma unroll
  for (int k = 0; k < 6; k++) {
    float g = 1.f/(1.f+expf(-s[k]));
    out_cg[((size_t)b*6+k)*HW + p] = (k==l) ? g : 0.f;
    if (k == l) gl = g;
  }
  float im = gl * ci[l];
  g_intens[(size_t)b*HW+p] = im;
  out_cond[(size_t)b*HW+p] = im*gl;
}

// ------------------------- f2: 1x1 conv GEMM  M=1176, N=HW per batch, K=256 -------------------------
__global__ __launch_bounds__(256) void f2_kernel(
    const float* __restrict__ A, const float* __restrict__ bias) {
  const int pb = blockIdx.x * 128;
  const int mb = blockIdx.y * 128;
  const int b = blockIdx.z;
  const int tid = threadIdx.x, tx = tid & 15, ty = tid >> 4;
  __shared__ float As[8][128];
  __shared__ float Bs[8][128];
  float acc[8][8];
  #pragma unroll
  for (int i = 0; i < 8; i++)
    #pragma unroll
    for (int j = 0; j < 8; j++) acc[i][j] = 0.f;
  const float* Bb = g_f1o + (size_t)b*256*HW + pb;
  for (int k0 = 0; k0 < 256; k0 += 8) {
    for (int i = tid; i < 1024; i += 256) {
      int m = i >> 3, k = i & 7;
      int gm = mb + m;
      As[k][m] = (gm < 1176) ? A[(size_t)gm*256 + k0 + k] : 0.f;
    }
    for (int i = tid; i < 1024; i += 256) {
      int k = i >> 7, p = i & 127;
      Bs[k][p] = Bb[(size_t)(k0+k)*HW + p];
    }
    __syncthreads();
    #pragma unroll
    for (int k = 0; k < 8; k++) {
      float a[8], bv[8];
      #pragma unroll
      for (int i = 0; i < 8; i++) a[i] = As[k][ty+i*16];
      #pragma unroll
      for (int j = 0; j < 8; j++) bv[j] = Bs[k][j*16+tx];
      #pragma unroll
      for (int i = 0; i < 8; i++)
        #pragma unroll
        for (int j = 0; j < 8; j++) acc[i][j] += a[i]*bv[j];
    }
    __syncthreads();
  }
  #pragma unroll
  for (int i = 0; i < 8; i++) {
    int m = mb + ty + i*16;
    if (m >= 1176) continue;
    float bs = bias[m];
    float* op = g_wbuf + ((size_t)b*1176 + m)*HW + pb;
    #pragma unroll
    for (int j = 0; j < 8; j++) op[j*16+tx] = acc[i][j] + bs;
  }
}

// ------------------------- scale by intensity + softmax over 49 taps (in place) ----------------
__global__ __launch_bounds__(256) void softmax_kernel() {
  size_t idx = (size_t)blockIdx.x*256 + threadIdx.x;  // over 4*24*HW
  int p = (int)(idx & 16383);
  int bc = (int)(idx >> 14);   // b*24+c
  int b = bc / 24;
  float im = g_intens[(size_t)b*HW + p];
  float* wp = g_wbuf + ((size_t)bc*49)*HW + p;
  float v[49]; float mx = -1e30f;
  #pragma unroll
  for (int t = 0; t < 49; t++) { v[t] = wp[(size_t)t*HW]*im; mx = fmaxf(mx, v[t]); }
  float s = 0.f;
  #pragma unroll
  for (int t = 0; t < 49; t++) { v[t] = expf(v[t]-mx); s += v[t]; }
  float inv = 1.f/s;
  #pragma unroll
  for (int t = 0; t < 49; t++) wp[(size_t)t*HW] = v[t]*inv;
}

// ------------------------- one diffusion step (edge-padded 7x7 per-pixel kernels) --------------
__global__ __launch_bounds__(256) void diffusion_kernel(const float* __restrict__ lat,
    float* __restrict__ out) {
  int tx = threadIdx.x & 31, ty = threadIdx.x >> 5;
  int x0 = blockIdx.x*32, y0 = blockIdx.y*8;
  int bc = blockIdx.z;                 // b*24+c
  __shared__ float sm[14][40];
  const float* lp = lat + (size_t)bc*HW;
  for (int i = threadIdx.x; i < 14*38; i += 256) {
    int r = i/38, c = i - r*38;
    int gy = min(max(y0 + r - 3, 0), 127);
    int gx = min(max(x0 + c - 3, 0), 127);
    sm[r][c] = lp[gy*128+gx];
  }
  __syncthreads();
  int x = x0+tx, y = y0+ty;
  const float* wp = g_wbuf + ((size_t)bc*49)*HW + y*128 + x;
  float acc = 0.f;
  #pragma unroll
  for (int t = 0; t < 49; t++) {
    int di = t/7, dj = t - di*7;
    acc += wp[(size_t)t*HW] * sm[ty+di][tx+dj];
  }
  out[(size_t)bc*HW + y*128 + x] = acc;
}

// ------------------------- launch -------------------------
extern "C" void kernel_launch(void* const* d_in, const int* in_sizes, int n_in,
                              void* d_out, int out_size) {
  const float* depth  = (const float*)d_in[0];
  const float* texf   = (const float*)d_in[1];
  const int*   labels = (const int*)d_in[2];
  const float* w_te1  = (const float*)d_in[3];
  const float* b_te1  = (const float*)d_in[4];
  const float* w_te2  = (const float*)d_in[5];
  const float* b_te2  = (const float*)d_in[6];
  const float* emb    = (const float*)d_in[7];
  const float* w_f1   = (const float*)d_in[8];
  const float* b_f1   = (const float*)d_in[9];
  const float* w_f2   = (const float*)d_in[10];
  const float* b_f2   = (const float*)d_in[11];
  const float* w_g1   = (const float*)d_in[12];
  const float* b_g1   = (const float*)d_in[13];
  const float* w_g2   = (const float*)d_in[14];
  const float* b_g2   = (const float*)d_in[15];
  const float* ci     = (const float*)d_in[16];
  float* out = (float*)d_out;

  float *t1, *tex, *g1b, *f1o, *latA, *latB;
  cudaGetSymbolAddress((void**)&t1,  g_t1);
  cudaGetSymbolAddress((void**)&tex, g_tex);
  cudaGetSymbolAddress((void**)&g1b, g_g1b);
  cudaGetSymbolAddress((void**)&f1o, g_f1o);
  cudaGetSymbolAddress((void**)&latA, g_latA);
  cudaGetSymbolAddress((void**)&latB, g_latB);

  // texture encoder
  te1_kernel<<<dim3(128,4), 128>>>(texf, w_te1, b_te1);
  conv3x3_kernel<64,128,true,false><<<dim3(128,1,4), 256>>>(t1, w_te2, b_te2, tex, 128, 64*9);
  // gate path
  conv3x3_kernel<128,64,true,false><<<dim3(128,1,4), 256>>>(tex, w_g1, b_g1, g1b, 64, 128*9);
  gate_kernel<<<dim3(64,4), 256>>>(w_g2, b_g2, labels, ci,
                                   out + (size_t)4*24*HW,
                                   out + (size_t)4*24*HW + (size_t)4*6*HW);
  // fusion path (emb half folded into per-tap constants)
  embS_kernel<<<36, 256>>>(w_f1, emb, labels);
  conv3x3_kernel<128,128,true,true><<<dim3(128,2,4), 256>>>(tex, w_f1, b_f1, f1o, 256, 256*9);
  f2_kernel<<<dim3(128,10,4), 256>>>(w_f2, b_f2);
  softmax_kernel<<<6144, 256>>>();

  // 8 diffusion steps (ping-pong), final step into d_out region 0
  diffusion_kernel<<<dim3(4,16,96), 256>>>(depth, latA);
  diffusion_kernel<<<dim3(4,16,96), 256>>>(latA, latB);
  diffusion_kernel<<<dim3(4,16,96), 256>>>(latB, latA);
  diffusion_kernel<<<dim3(4,16,96), 256>>>(latA, latB);
  diffusion_kernel<<<dim3(4,16,96), 256>>>(latB, latA);
  diffusion_kernel<<<dim3(4,16,96), 256>>>(latA, latB);
  diffusion_kernel<<<dim3(4,16,96), 256>>>(latB, latA);
  diffusion_kernel<<<dim3(4,16,96), 256>>>(latA, out);
}

// round 6
// speedup vs baseline: 2.2726x; 2.2726x over previous
#include <cuda_runtime.h>
#include <math.h>
#include <stdint.h>

#define HW 16384

// ------------------------- scratch (static device globals) -------------------------
__device__ float g_t1[(size_t)4*64*HW];      // te1 out
__device__ float g_tex[(size_t)4*128*HW];    // te2 out (tex)
__device__ float g_g1b[(size_t)4*64*HW];     // g1 out
__device__ float g_f1o[(size_t)4*256*HW];    // f1 out
__device__ float g_wbuf[(size_t)4*1176*HW];  // f2 out -> softmax'd weights
__device__ float g_latA[(size_t)4*24*HW];
__device__ float g_latB[(size_t)4*24*HW];
__device__ float g_intens[(size_t)4*HW];     // intensity map
__device__ float g_S[4*256*9];               // emb tap sums for f1
__device__ float g_wt[9*128*256];            // w_f1 tex-half transposed [tap][ic][oc], tf32-rounded

// tf32 round-to-nearest (so HW truncation inside HMMA is exact afterwards)
__device__ __forceinline__ uint32_t to_tf32(float x) {
  uint32_t o;
  asm("cvt.rna.tf32.f32 %0, %1;" : "=r"(o) : "f"(x));
  return o;
}
__device__ __forceinline__ float tf32f(float x) { return __uint_as_float(to_tf32(x)); }

__device__ __forceinline__ void mma_tf32(float* c, const uint32_t* a, const uint32_t* b) {
  asm volatile("mma.sync.aligned.m16n8k8.row.col.f32.tf32.tf32.f32 "
    "{%0,%1,%2,%3}, {%4,%5,%6,%7}, {%8,%9}, {%0,%1,%2,%3};"
    : "+f"(c[0]), "+f"(c[1]), "+f"(c[2]), "+f"(c[3])
    : "r"(a[0]), "r"(a[1]), "r"(a[2]), "r"(a[3]), "r"(b[0]), "r"(b[1]));
}

// ------------------------- te1: 3->64 conv3x3 + relu -------------------------
__global__ __launch_bounds__(128) void te1_kernel(const float* __restrict__ in,
    const float* __restrict__ w, const float* __restrict__ bias) {
  int y = blockIdx.x, b = blockIdx.y, x = threadIdx.x;
  __shared__ float Ws[64*27];
  __shared__ float bsh[64];
  for (int i = threadIdx.x; i < 64*27; i += 128) Ws[i] = w[i];
  if (threadIdx.x < 64) bsh[threadIdx.x] = bias[threadIdx.x];
  __syncthreads();
  float iv[27];
  #pragma unroll
  for (int c = 0; c < 3; c++)
    #pragma unroll
    for (int ki = 0; ki < 3; ki++)
      #pragma unroll
      for (int kj = 0; kj < 3; kj++) {
        int gy = y + ki - 1, gx = x + kj - 1;
        iv[c*9+ki*3+kj] = ((unsigned)gy < 128u && (unsigned)gx < 128u)
            ? in[((b*3+c)*128+gy)*128+gx] : 0.f;
      }
  for (int oc = 0; oc < 64; oc++) {
    float s = bsh[oc];
    #pragma unroll
    for (int k = 0; k < 27; k++) s += Ws[oc*27+k] * iv[k];
    g_t1[(((size_t)b*64+oc)*128+y)*128+x] = fmaxf(s, 0.f);
  }
}

// ------------------------- generic conv3x3 (zero pad), register-tiled FFMA ------------
template<int CIN, int BM, bool RELU>
__global__ __launch_bounds__(256) void conv3x3_kernel(
    const float* __restrict__ in, const float* __restrict__ w,
    const float* __restrict__ bias, float* __restrict__ out,
    int cout, int wstride) {
  constexpr int IT = BM/16;
  const int y = blockIdx.x;
  const int ocb = blockIdx.y * BM;
  const int b = blockIdx.z;
  const int tid = threadIdx.x, tx = tid & 15, ty = tid >> 4;

  __shared__ float Ws[BM][4][9];
  __shared__ float Bs[4][3][132];

  float acc[IT][8];
  #pragma unroll
  for (int i = 0; i < IT; i++)
    #pragma unroll
    for (int j = 0; j < 8; j++) acc[i][j] = 0.f;

  const float* inB = in + (size_t)b*CIN*HW;

  for (int ic0 = 0; ic0 < CIN; ic0 += 4) {
    for (int idx = tid; idx < BM*36; idx += 256) {
      int oc = idx/36, r = idx%36, ic = r/9, tap = r%9;
      float v = 0.f;
      if (ocb + oc < cout)
        v = w[(size_t)(ocb+oc)*wstride + (ic0+ic)*9 + tap];
      Ws[oc][ic][tap] = v;
    }
    for (int idx = tid; idx < 4*3*130; idx += 256) {
      int ic = idx/390, r = idx%390, ki = r/130, col = r%130;
      int gy = y + ki - 1, gx = col - 1;
      float v = 0.f;
      if ((unsigned)gy < 128u && (unsigned)gx < 128u)
        v = inB[(size_t)(ic0+ic)*HW + gy*128 + gx];
      Bs[ic][ki][col] = v;
    }
    __syncthreads();
    #pragma unroll
    for (int ic = 0; ic < 4; ic++) {
      #pragma unroll
      for (int ki = 0; ki < 3; ki++) {
        #pragma unroll
        for (int kj = 0; kj < 3; kj++) {
          float a[IT];
          #pragma unroll
          for (int i = 0; i < IT; i++) a[i] = Ws[ty + i*16][ic][ki*3+kj];
          #pragma unroll
          for (int j = 0; j < 8; j++) {
            float bv = Bs[ic][ki][j*16 + tx + kj];
            #pragma unroll
            for (int i = 0; i < IT; i++) acc[i][j] += a[i]*bv;
          }
        }
      }
    }
    __syncthreads();
  }
  #pragma unroll
  for (int i = 0; i < IT; i++) {
    int oc = ocb + ty + i*16;
    if (oc >= cout) continue;
    float bs = bias[oc];
    float* op = out + (((size_t)b*cout + oc)*128 + y)*128;
    #pragma unroll
    for (int j = 0; j < 8; j++) {
      float v = acc[i][j] + bs;
      if (RELU) v = fmaxf(v, 0.f);
      op[j*16 + tx] = v;
    }
  }
}

// ------------------------- emb tap sums -------------------------
__global__ void embS_kernel(const float* __restrict__ wf1,
    const float* __restrict__ emb, const int* __restrict__ labels) {
  int idx = blockIdx.x*256 + threadIdx.x;
  if (idx >= 4*256*9) return;
  int b = idx/(256*9); int r = idx - b*2304; int o = r/9; int tap = r - o*9;
  int l = labels[b];
  float s = 0.f;
  for (int c = 0; c < 128; c++)
    s += wf1[(size_t)o*2304 + (128+c)*9 + tap] * emb[l*128+c];
  g_S[idx] = s;
}

// ------------------------- w_f1 transpose (tex half) to [tap][ic][oc], tf32 --------------
__global__ void wtrans_kernel(const float* __restrict__ wf1) {
  int idx = blockIdx.x*256 + threadIdx.x;   // 9*128*256
  if (idx >= 294912) return;
  int t = idx >> 15;          // /32768
  int r = idx & 32767;
  int ic = r >> 8, oc = r & 255;
  g_wt[idx] = tf32f(wf1[(size_t)oc*2304 + ic*9 + t]);
}

// ------------------------- gate -------------------------
__global__ __launch_bounds__(256) void gate_kernel(const float* __restrict__ wg2,
    const float* __restrict__ bg2, const int* __restrict__ labels,
    const float* __restrict__ ci, float* __restrict__ out_cg,
    float* __restrict__ out_cond) {
  int p = blockIdx.x*256 + threadIdx.x;
  int b = blockIdx.y;
  __shared__ float Ws[6*64];
  for (int i = threadIdx.x; i < 384; i += 256) Ws[i] = wg2[i];
  __syncthreads();
  float s[6];
  #pragma unroll
  for (int k = 0; k < 6; k++) s[k] = bg2[k];
  const float* gp = g_g1b + (size_t)b*64*HW + p;
  #pragma unroll
  for (int c = 0; c < 64; c++) {
    float v = gp[(size_t)c*HW];
    #pragma unroll
    for (int k = 0; k < 6; k++) s[k] += Ws[k*64+c]*v;
  }
  int l = labels[b];
  float gl = 0.f;
  #pragma unroll
  for (int k = 0; k < 6; k++) {
    float g = 1.f/(1.f+expf(-s[k]));
    out_cg[((size_t)b*6+k)*HW + p] = (k==l) ? g : 0.f;
    if (k == l) gl = g;
  }
  float im = gl * ci[l];
  g_intens[(size_t)b*HW+p] = im;
  out_cond[(size_t)b*HW+p] = im*gl;
}

// ========================= f2 via mma.sync tf32 =========================
// C[m][p] = sum_k A[m][k]*B[k][p]; A = w_f2 [1176][256], B = g_f1o[b][256][16384].
__global__ __launch_bounds__(256) void f2_mma_kernel(
    const float* __restrict__ A, const float* __restrict__ bias) {
  __shared__ float As[128][36];    // [m][k] pad 36
  __shared__ float Bs[32][136];    // [k][n] pad 136
  const int pb = blockIdx.x * 128;
  const int mb = blockIdx.y * 128;
  const int b  = blockIdx.z;
  const int tid = threadIdx.x, lane = tid & 31, wid = tid >> 5;
  const int warpM = wid >> 2, warpN = wid & 3;

  float acc[4][4][4];
  #pragma unroll
  for (int i = 0; i < 4; i++)
    #pragma unroll
    for (int j = 0; j < 4; j++)
      #pragma unroll
      for (int c = 0; c < 4; c++) acc[i][j][c] = 0.f;

  const float* Bb = g_f1o + (size_t)b*256*HW + pb;

  for (int kc = 0; kc < 8; kc++) {
    const int k0 = kc * 32;
    // A: 1024 float4 slots, [m][k]
    #pragma unroll
    for (int it = 0; it < 4; it++) {
      int s = tid + it*256;
      int m = s >> 3, kb = (s & 7) * 4;
      float4 f = make_float4(0.f,0.f,0.f,0.f);
      if (mb + m < 1176) f = *(const float4*)(A + (size_t)(mb+m)*256 + k0 + kb);
      float4 o; o.x = tf32f(f.x); o.y = tf32f(f.y); o.z = tf32f(f.z); o.w = tf32f(f.w);
      *(float4*)&As[m][kb] = o;
    }
    // B: 1024 float4 slots, [k][n]
    #pragma unroll
    for (int it = 0; it < 4; it++) {
      int s = tid + it*256;
      int k = s >> 5, nb = (s & 31) * 4;
      float4 f = *(const float4*)(Bb + (size_t)(k0+k)*HW + nb);
      float4 o; o.x = tf32f(f.x); o.y = tf32f(f.y); o.z = tf32f(f.z); o.w = tf32f(f.w);
      *(float4*)&Bs[k][nb] = o;
    }
    __syncthreads();
    #pragma unroll
    for (int s = 0; s < 4; s++) {
      const int ka = s*8 + (lane & 3);
      const int mrow = warpM*64 + (lane >> 2);
      const int ncol = warpN*32 + (lane >> 2);
      uint32_t a[4][4], bf[4][2];
      #pragma unroll
      for (int mt = 0; mt < 4; mt++) {
        a[mt][0] = __float_as_uint(As[mrow + mt*16    ][ka]);
        a[mt][1] = __float_as_uint(As[mrow + mt*16 + 8][ka]);
        a[mt][2] = __float_as_uint(As[mrow + mt*16    ][ka+4]);
        a[mt][3] = __float_as_uint(As[mrow + mt*16 + 8][ka+4]);
      }
      #pragma unroll
      for (int nt = 0; nt < 4; nt++) {
        bf[nt][0] = __float_as_uint(Bs[ka  ][ncol + nt*8]);
        bf[nt][1] = __float_as_uint(Bs[ka+4][ncol + nt*8]);
      }
      #pragma unroll
      for (int mt = 0; mt < 4; mt++)
        #pragma unroll
        for (int nt = 0; nt < 4; nt++)
          mma_tf32(acc[mt][nt], a[mt], bf[nt]);
    }
    __syncthreads();
  }
  // epilogue
  #pragma unroll
  for (int mt = 0; mt < 4; mt++) {
    int m0 = mb + warpM*64 + mt*16 + (lane >> 2);
    int m1 = m0 + 8;
    float bv0 = (m0 < 1176) ? bias[m0] : 0.f;
    float bv1 = (m1 < 1176) ? bias[m1] : 0.f;
    float* r0 = g_wbuf + ((size_t)b*1176 + m0)*HW + pb;
    float* r1 = g_wbuf + ((size_t)b*1176 + m1)*HW + pb;
    #pragma unroll
    for (int nt = 0; nt < 4; nt++) {
      int p = warpN*32 + nt*8 + (lane & 3)*2;
      if (m0 < 1176) { float2 v; v.x = acc[mt][nt][0]+bv0; v.y = acc[mt][nt][1]+bv0; *(float2*)(r0+p) = v; }
      if (m1 < 1176) { float2 v; v.x = acc[mt][nt][2]+bv1; v.y = acc[mt][nt][3]+bv1; *(float2*)(r1+p) = v; }
    }
  }
}

// ========================= f1 via mma.sync tf32 (9 shifted GEMMs) =========================
// out[o][y][x] = relu(bias[o] + sum_{ki,kj,c} W[o][c][tap]*tex[c][y+ki-1][x+kj-1] + embS terms)
// block: one row y, 128 oc (mb of 2), 128 px. dyn smem: As[3][32][136] + Bs[32][136].
__global__ __launch_bounds__(256) void f1_mma_kernel(
    const float* __restrict__ bias) {
  extern __shared__ float f1s[];
  float* As = f1s;                 // [kj][k][136] -> kj*4352 + k*136 + m
  float* Bs = f1s + 3*32*136;      // [k][136], col = gx+1
  __shared__ float Ssum[128][4];

  const int y  = blockIdx.x;
  const int mb = blockIdx.y * 128;
  const int b  = blockIdx.z;
  const int tid = threadIdx.x, lane = tid & 31, wid = tid >> 5;
  const int warpM = wid >> 2, warpN = wid & 3;

  // per-(oc,kj) column sums of emb tap constants over valid ki (y known)
  for (int i = tid; i < 384; i += 256) {
    int oc = i / 3, kj = i - oc*3;
    float s = 0.f;
    #pragma unroll
    for (int ki = 0; ki < 3; ki++)
      if ((unsigned)(y + ki - 1) < 128u)
        s += g_S[(b*256 + mb + oc)*9 + ki*3 + kj];
    Ssum[oc][kj] = s;
  }

  float acc[4][4][4];
  #pragma unroll
  for (int i = 0; i < 4; i++)
    #pragma unroll
    for (int j = 0; j < 4; j++)
      #pragma unroll
      for (int c = 0; c < 4; c++) acc[i][j][c] = 0.f;

  for (int ki = 0; ki < 3; ki++) {
    int gy = y + ki - 1;
    if ((unsigned)gy >= 128u) continue;
    for (int cc = 0; cc < 4; cc++) {
      // stage B: 32 channels x 132 cols (col = gx+1, zero halo)
      const float* texrow = g_tex + (size_t)(b*128 + cc*32)*HW + gy*128;
      for (int idx = tid; idx < 32*132; idx += 256) {
        int k = idx / 132, col = idx - k*132;
        int gx = col - 1;
        float v = 0.f;
        if ((unsigned)gx < 128u) v = tf32f(texrow[(size_t)k*HW + gx]);
        Bs[k*136 + col] = v;
      }
      // stage A: 3 kj taps, [k][m] from g_wt[tap][ic][oc] (coalesced float4 along oc)
      #pragma unroll
      for (int it = 0; it < 12; it++) {
        int s = tid + it*256;            // 3072 slots
        int kj = s >> 10;
        int r = s & 1023;
        int k = r >> 5, m4 = (r & 31) * 4;
        float4 f = *(const float4*)(g_wt + (size_t)((ki*3+kj)*128 + cc*32 + k)*256 + mb + m4);
        *(float4*)&As[kj*4352 + k*136 + m4] = f;
      }
      __syncthreads();
      #pragma unroll
      for (int kj = 0; kj < 3; kj++) {
        const float* Akj = As + kj*4352;
        #pragma unroll
        for (int s = 0; s < 4; s++) {
          const int ka = s*8 + (lane & 3);
          const int mrow = warpM*64 + (lane >> 2);
          const int col0 = warpN*32 + (lane >> 2) + kj;   // col = x + kj
          uint32_t a[4][4], bf[4][2];
          #pragma unroll
          for (int mt = 0; mt < 4; mt++) {
            a[mt][0] = __float_as_uint(Akj[(ka  )*136 + mrow + mt*16    ]);
            a[mt][1] = __float_as_uint(Akj[(ka  )*136 + mrow + mt*16 + 8]);
            a[mt][2] = __float_as_uint(Akj[(ka+4)*136 + mrow + mt*16    ]);
            a[mt][3] = __float_as_uint(Akj[(ka+4)*136 + mrow + mt*16 + 8]);
          }
          #pragma unroll
          for (int nt = 0; nt < 4; nt++) {
            bf[nt][0] = __float_as_uint(Bs[(ka  )*136 + col0 + nt*8]);
            bf[nt][1] = __float_as_uint(Bs[(ka+4)*136 + col0 + nt*8]);
          }
          #pragma unroll
          for (int mt = 0; mt < 4; mt++)
            #pragma unroll
            for (int nt = 0; nt < 4; nt++)
              mma_tf32(acc[mt][nt], a[mt], bf[nt]);
        }
      }
      __syncthreads();
    }
  }

  // epilogue: bias + emb tap sums (x-border masked) + relu
  #pragma unroll
  for (int mt = 0; mt < 4; mt++) {
    #pragma unroll
    for (int h = 0; h < 2; h++) {
      int ocl = warpM*64 + mt*16 + (lane >> 2) + h*8;
      int oc = mb + ocl;
      float bv = bias[oc];
      float s0 = Ssum[ocl][0], s1 = Ssum[ocl][1], s2 = Ssum[ocl][2];
      float* op = g_f1o + ((size_t)(b*256 + oc)*128 + y)*128;
      #pragma unroll
      for (int nt = 0; nt < 4; nt++) {
        int x = warpN*32 + nt*8 + (lane & 3)*2;
        float t0 = s1 + (x > 0   ? s0 : 0.f) + (x < 127   ? s2 : 0.f);
        float t1 = s1 + (x+1 > 0 ? s0 : 0.f) + (x+1 < 127 ? s2 : 0.f);
        float2 v;
        v.x = fmaxf(acc[mt][nt][h*2+0] + bv + t0, 0.f);
        v.y = fmaxf(acc[mt][nt][h*2+1] + bv + t1, 0.f);
        *(float2*)(op + x) = v;
      }
    }
  }
}

// ------------------------- scale by intensity + softmax over 49 taps ----------------
__global__ __launch_bounds__(256) void softmax_kernel() {
  size_t idx = (size_t)blockIdx.x*256 + threadIdx.x;
  int p = (int)(idx & 16383);
  int bc = (int)(idx >> 14);
  int b = bc / 24;
  float im = g_intens[(size_t)b*HW + p];
  float* wp = g_wbuf + ((size_t)bc*49)*HW + p;
  float v[49]; float mx = -1e30f;
  #pragma unroll
  for (int t = 0; t < 49; t++) { v[t] = wp[(size_t)t*HW]*im; mx = fmaxf(mx, v[t]); }
  float s = 0.f;
  #pragma unroll
  for (int t = 0; t < 49; t++) { v[t] = expf(v[t]-mx); s += v[t]; }
  float inv = 1.f/s;
  #pragma unroll
  for (int t = 0; t < 49; t++) wp[(size_t)t*HW] = v[t]*inv;
}

// ------------------------- one diffusion step --------------
__global__ __launch_bounds__(256) void diffusion_kernel(const float* __restrict__ lat,
    float* __restrict__ out) {
  int tx = threadIdx.x & 31, ty = threadIdx.x >> 5;
  int x0 = blockIdx.x*32, y0 = blockIdx.y*8;
  int bc = blockIdx.z;
  __shared__ float sm[14][40];
  const float* lp = lat + (size_t)bc*HW;
  for (int i = threadIdx.x; i < 14*38; i += 256) {
    int r = i/38, c = i - r*38;
    int gy = min(max(y0 + r - 3, 0), 127);
    int gx = min(max(x0 + c - 3, 0), 127);
    sm[r][c] = lp[gy*128+gx];
  }
  __syncthreads();
  int x = x0+tx, y = y0+ty;
  const float* wp = g_wbuf + ((size_t)bc*49)*HW + y*128 + x;
  float acc = 0.f;
  #pragma unroll
  for (int t = 0; t < 49; t++) {
    int di = t/7, dj = t - di*7;
    acc += wp[(size_t)t*HW] * sm[ty+di][tx+dj];
  }
  out[(size_t)bc*HW + y*128 + x] = acc;
}

// ------------------------- launch -------------------------
extern "C" void kernel_launch(void* const* d_in, const int* in_sizes, int n_in,
                              void* d_out, int out_size) {
  const float* depth  = (const float*)d_in[0];
  const float* texf   = (const float*)d_in[1];
  const int*   labels = (const int*)d_in[2];
  const float* w_te1  = (const float*)d_in[3];
  const float* b_te1  = (const float*)d_in[4];
  const float* w_te2  = (const float*)d_in[5];
  const float* b_te2  = (const float*)d_in[6];
  const float* emb    = (const float*)d_in[7];
  const float* w_f1   = (const float*)d_in[8];
  const float* b_f1   = (const float*)d_in[9];
  const float* w_f2   = (const float*)d_in[10];
  const float* b_f2   = (const float*)d_in[11];
  const float* w_g1   = (const float*)d_in[12];
  const float* b_g1   = (const float*)d_in[13];
  const float* w_g2   = (const float*)d_in[14];
  const float* b_g2   = (const float*)d_in[15];
  const float* ci     = (const float*)d_in[16];
  float* out = (float*)d_out;

  float *t1, *tex, *g1b, *latA, *latB;
  cudaGetSymbolAddress((void**)&t1,  g_t1);
  cudaGetSymbolAddress((void**)&tex, g_tex);
  cudaGetSymbolAddress((void**)&g1b, g_g1b);
  cudaGetSymbolAddress((void**)&latA, g_latA);
  cudaGetSymbolAddress((void**)&latB, g_latB);

  static bool attr_set = false;
  if (!attr_set) {
    cudaFuncSetAttribute(f1_mma_kernel, cudaFuncAttributeMaxDynamicSharedMemorySize, 69632);
    attr_set = true;
  }

  // texture encoder
  te1_kernel<<<dim3(128,4), 128>>>(texf, w_te1, b_te1);
  conv3x3_kernel<64,128,true><<<dim3(128,1,4), 256>>>(t1, w_te2, b_te2, tex, 128, 64*9);
  // gate path
  conv3x3_kernel<128,64,true><<<dim3(128,1,4), 256>>>(tex, w_g1, b_g1, g1b, 64, 128*9);
  gate_kernel<<<dim3(64,4), 256>>>(w_g2, b_g2, labels, ci,
                                   out + (size_t)4*24*HW,
                                   out + (size_t)4*24*HW + (size_t)4*6*HW);
  // fusion path
  embS_kernel<<<36, 256>>>(w_f1, emb, labels);
  wtrans_kernel<<<1152, 256>>>(w_f1);
  f1_mma_kernel<<<dim3(128,2,4), 256, 69632>>>(b_f1);
  f2_mma_kernel<<<dim3(128,10,4), 256>>>(w_f2, b_f2);
  softmax_kernel<<<6144, 256>>>();

  // 8 diffusion steps (ping-pong), final into d_out
  diffusion_kernel<<<dim3(4,16,96), 256>>>(depth, latA);
  diffusion_kernel<<<dim3(4,16,96), 256>>>(latA, latB);
  diffusion_kernel<<<dim3(4,16,96), 256>>>(latB, latA);
  diffusion_kernel<<<dim3(4,16,96), 256>>>(latA, latB);
  diffusion_kernel<<<dim3(4,16,96), 256>>>(latB, latA);
  diffusion_kernel<<<dim3(4,16,96), 256>>>(latA, latB);
  diffusion_kernel<<<dim3(4,16,96), 256>>>(latB, latA);
  diffusion_kernel<<<dim3(4,16,96), 256>>>(latA, out);
}

// round 7
// speedup vs baseline: 3.7148x; 1.6346x over previous
#include <cuda_runtime.h>
#include <math.h>
#include <stdint.h>

#define HW 16384

// ------------------------- scratch (static device globals) -------------------------
__device__ float g_t1[(size_t)4*64*HW];      // te1 out
__device__ float g_tex[(size_t)4*128*HW];    // te2 out (tex)
__device__ float g_g1b[(size_t)4*64*HW];     // g1 out
__device__ float g_f1o[(size_t)4*256*HW];    // f1 out
__device__ float g_wbuf[(size_t)4*1176*HW];  // f2 out (logits)
__device__ unsigned short g_wq[(size_t)4*1176*HW];  // softmax weights, u16 fixed point
__device__ float g_latA[(size_t)4*24*HW];
__device__ float g_latB[(size_t)4*24*HW];
__device__ float g_intens[(size_t)4*HW];     // intensity map
__device__ float g_S[4*256*9];               // emb tap sums for f1
__device__ float g_wt [9*128*256];           // w_f1 tex-half  [tap][ic][oc] tf32
__device__ float g_wt2[9*64*128];            // w_te2          [tap][ic][oc] tf32
__device__ float g_wtg[9*128*64];            // w_g1           [tap][ic][oc] tf32

// tf32 round-to-nearest (so HW truncation inside HMMA is exact afterwards)
__device__ __forceinline__ uint32_t to_tf32(float x) {
  uint32_t o;
  asm("cvt.rna.tf32.f32 %0, %1;" : "=r"(o) : "f"(x));
  return o;
}
__device__ __forceinline__ float tf32f(float x) { return __uint_as_float(to_tf32(x)); }

__device__ __forceinline__ void mma_tf32(float* c, const uint32_t* a, const uint32_t* b) {
  asm volatile("mma.sync.aligned.m16n8k8.row.col.f32.tf32.tf32.f32 "
    "{%0,%1,%2,%3}, {%4,%5,%6,%7}, {%8,%9}, {%0,%1,%2,%3};"
    : "+f"(c[0]), "+f"(c[1]), "+f"(c[2]), "+f"(c[3])
    : "r"(a[0]), "r"(a[1]), "r"(a[2]), "r"(a[3]), "r"(b[0]), "r"(b[1]));
}

// ------------------------- te1: 3->64 conv3x3 + relu -------------------------
__global__ __launch_bounds__(128) void te1_kernel(const float* __restrict__ in,
    const float* __restrict__ w, const float* __restrict__ bias) {
  int y = blockIdx.x, b = blockIdx.y, x = threadIdx.x;
  __shared__ float Ws[64*27];
  __shared__ float bsh[64];
  for (int i = threadIdx.x; i < 64*27; i += 128) Ws[i] = w[i];
  if (threadIdx.x < 64) bsh[threadIdx.x] = bias[threadIdx.x];
  __syncthreads();
  float iv[27];
  #pragma unroll
  for (int c = 0; c < 3; c++)
    #pragma unroll
    for (int ki = 0; ki < 3; ki++)
      #pragma unroll
      for (int kj = 0; kj < 3; kj++) {
        int gy = y + ki - 1, gx = x + kj - 1;
        iv[c*9+ki*3+kj] = ((unsigned)gy < 128u && (unsigned)gx < 128u)
            ? in[((b*3+c)*128+gy)*128+gx] : 0.f;
      }
  for (int oc = 0; oc < 64; oc++) {
    float s = bsh[oc];
    #pragma unroll
    for (int k = 0; k < 27; k++) s += Ws[oc*27+k] * iv[k];
    g_t1[(((size_t)b*64+oc)*128+y)*128+x] = fmaxf(s, 0.f);
  }
}

// ------------------------- weight transpose to [tap][ic][cout], tf32 -------------------------
// src layout: w[oc][*][9] with row stride wstride (allows taking a cin-slice of w_f1)
__global__ void wtrans_kernel(const float* __restrict__ w, float* __restrict__ outw,
                              int cin, int cout, int wstride, int total) {
  int idx = blockIdx.x*256 + threadIdx.x;
  if (idx >= total) return;
  int t = idx / (cin*cout);
  int r = idx - t*(cin*cout);
  int ic = r / cout, oc = r - ic*cout;
  outw[idx] = tf32f(w[(size_t)oc*wstride + ic*9 + t]);
}

// ------------------------- emb tap sums -------------------------
__global__ void embS_kernel(const float* __restrict__ wf1,
    const float* __restrict__ emb, const int* __restrict__ labels) {
  int idx = blockIdx.x*256 + threadIdx.x;
  if (idx >= 4*256*9) return;
  int b = idx/(256*9); int r = idx - b*2304; int o = r/9; int tap = r - o*9;
  int l = labels[b];
  float s = 0.f;
  for (int c = 0; c < 128; c++)
    s += wf1[(size_t)o*2304 + (128+c)*9 + tap] * emb[l*128+c];
  g_S[idx] = s;
}

// ========================= generic conv3x3 via mma.sync tf32 =========================
// 9 shifted GEMMs. Block = one image row y x MT output channels x 128 px.
// wt layout [tap][CIN][cout_total] (pre-tf32). EMB adds class-emb tap constants (f1 only).
template<int CIN, int MT, bool EMB>
__global__ __launch_bounds__(256) void conv_mma_kernel(
    const float* __restrict__ wt, const float* __restrict__ bias,
    const float* __restrict__ in, float* __restrict__ out, int cout_total) {
  constexpr int WM = MT/64;          // warps along M: 2 (MT=128) or 1 (MT=64)
  constexpr int WN = 8/WM;           // warps along N: 4 or 8
  constexpr int NT = 16/WN;          // 8-wide n tiles per warp: 4 or 2
  constexpr int NW = 128/WN;         // px per warp: 32 or 16
  constexpr int SM = MT + 8;         // A smem stride
  constexpr int MPR = MT/4;          // float4 slots per k-row of A

  extern __shared__ float cms[];
  float* As = cms;                   // [3][32][SM]
  float* Bs = cms + 3*32*SM;         // [32][136], col = gx+1
  __shared__ float Ssum[MT][4];

  const int y  = blockIdx.x;
  const int mb = blockIdx.y * MT;
  const int b  = blockIdx.z;
  const int tid = threadIdx.x, lane = tid & 31, wid = tid >> 5;
  const int warpM = wid / WN, warpN = wid % WN;

  if (EMB) {
    for (int i = tid; i < MT*3; i += 256) {
      int oc = i / 3, kj = i - oc*3;
      float s = 0.f;
      #pragma unroll
      for (int ki = 0; ki < 3; ki++)
        if ((unsigned)(y + ki - 1) < 128u)
          s += g_S[(b*256 + mb + oc)*9 + ki*3 + kj];
      Ssum[oc][kj] = s;
    }
  }

  float acc[4][NT][4];
  #pragma unroll
  for (int i = 0; i < 4; i++)
    #pragma unroll
    for (int j = 0; j < NT; j++)
      #pragma unroll
      for (int c = 0; c < 4; c++) acc[i][j][c] = 0.f;

  for (int ki = 0; ki < 3; ki++) {
    int gy = y + ki - 1;
    if ((unsigned)gy >= 128u) continue;
    for (int cc = 0; cc < CIN/32; cc++) {
      // stage B: 32 channels x 132 cols (zero halo)
      const float* srcrow = in + (size_t)(b*CIN + cc*32)*HW + gy*128;
      for (int idx = tid; idx < 32*132; idx += 256) {
        int k = idx / 132, col = idx - k*132;
        int gx = col - 1;
        float v = 0.f;
        if ((unsigned)gx < 128u) v = tf32f(srcrow[(size_t)k*HW + gx]);
        Bs[k*136 + col] = v;
      }
      // stage A: 3 kj taps x 32 k x MT oc (float4 along oc)
      #pragma unroll
      for (int it = 0; it < 3*32*MPR/256; it++) {
        int s = tid + it*256;
        int kj = s / (32*MPR);
        int r = s - kj*(32*MPR);
        int k = r / MPR, m4 = (r - k*MPR) * 4;
        float4 f = *(const float4*)(wt + (size_t)((ki*3+kj)*CIN + cc*32 + k)*cout_total + mb + m4);
        *(float4*)&As[kj*32*SM + k*SM + m4] = f;
      }
      __syncthreads();
      #pragma unroll
      for (int kj = 0; kj < 3; kj++) {
        const float* Akj = As + kj*32*SM;
        #pragma unroll
        for (int s = 0; s < 4; s++) {
          const int ka = s*8 + (lane & 3);
          const int mrow = warpM*64 + (lane >> 2);
          const int col0 = warpN*NW + (lane >> 2) + kj;
          uint32_t a[4][4], bf[NT][2];
          #pragma unroll
          for (int mt = 0; mt < 4; mt++) {
            a[mt][0] = __float_as_uint(Akj[(ka  )*SM + mrow + mt*16    ]);
            a[mt][1] = __float_as_uint(Akj[(ka  )*SM + mrow + mt*16 + 8]);
            a[mt][2] = __float_as_uint(Akj[(ka+4)*SM + mrow + mt*16    ]);
            a[mt][3] = __float_as_uint(Akj[(ka+4)*SM + mrow + mt*16 + 8]);
          }
          #pragma unroll
          for (int nt = 0; nt < NT; nt++) {
            bf[nt][0] = __float_as_uint(Bs[(ka  )*136 + col0 + nt*8]);
            bf[nt][1] = __float_as_uint(Bs[(ka+4)*136 + col0 + nt*8]);
          }
          #pragma unroll
          for (int mt = 0; mt < 4; mt++)
            #pragma unroll
            for (int nt = 0; nt < NT; nt++)
              mma_tf32(acc[mt][nt], a[mt], bf[nt]);
        }
      }
      __syncthreads();
    }
  }

  // epilogue: bias (+ emb tap sums, x-border masked) + relu
  #pragma unroll
  for (int mt = 0; mt < 4; mt++) {
    #pragma unroll
    for (int h = 0; h < 2; h++) {
      int ocl = warpM*64 + mt*16 + (lane >> 2) + h*8;
      int oc = mb + ocl;
      float bv = bias[oc];
      float* op = out + (((size_t)b*cout_total + oc)*128 + y)*128;
      float s0 = 0.f, s1 = 0.f, s2 = 0.f;
      if (EMB) { s0 = Ssum[ocl][0]; s1 = Ssum[ocl][1]; s2 = Ssum[ocl][2]; }
      #pragma unroll
      for (int nt = 0; nt < NT; nt++) {
        int x = warpN*NW + nt*8 + (lane & 3)*2;
        float t0 = 0.f, t1 = 0.f;
        if (EMB) {
          t0 = s1 + (x > 0   ? s0 : 0.f) + (x < 127   ? s2 : 0.f);
          t1 = s1 + s0 + (x+1 < 127 ? s2 : 0.f);   // x+1 >= 1 always
        }
        float2 v;
        v.x = fmaxf(acc[mt][nt][h*2+0] + bv + t0, 0.f);
        v.y = fmaxf(acc[mt][nt][h*2+1] + bv + t1, 0.f);
        *(float2*)(op + x) = v;
      }
    }
  }
}

// ------------------------- gate -------------------------
__global__ __launch_bounds__(256) void gate_kernel(const float* __restrict__ wg2,
    const float* __restrict__ bg2, const int* __restrict__ labels,
    const float* __restrict__ ci, float* __restrict__ out_cg,
    float* __restrict__ out_cond) {
  int p = blockIdx.x*256 + threadIdx.x;
  int b = blockIdx.y;
  __shared__ float Ws[6*64];
  for (int i = threadIdx.x; i < 384; i += 256) Ws[i] = wg2[i];
  __syncthreads();
  float s[6];
  #pragma unroll
  for (int k = 0; k < 6; k++) s[k] = bg2[k];
  const float* gp = g_g1b + (size_t)b*64*HW + p;
  #pragma unroll
  for (int c = 0; c < 64; c++) {
    float v = gp[(size_t)c*HW];
    #pragma unroll
    for (int k = 0; k < 6; k++) s[k] += Ws[k*64+c]*v;
  }
  int l = labels[b];
  float gl = 0.f;
  #pragma unroll
  for (int k = 0; k < 6; k++) {
    float g = 1.f/(1.f+expf(-s[k]));
    out_cg[((size_t)b*6+k)*HW + p] = (k==l) ? g : 0.f;
    if (k == l) gl = g;
  }
  float im = gl * ci[l];
  g_intens[(size_t)b*HW+p] = im;
  out_cond[(size_t)b*HW+p] = im*gl;
}

// ========================= f2 via mma.sync tf32 =========================
__global__ __launch_bounds__(256) void f2_mma_kernel(
    const float* __restrict__ A, const float* __restrict__ bias) {
  __shared__ float As[128][36];
  __shared__ float Bs[32][136];
  const int pb = blockIdx.x * 128;
  const int mb = blockIdx.y * 128;
  const int b  = blockIdx.z;
  const int tid = threadIdx.x, lane = tid & 31, wid = tid >> 5;
  const int warpM = wid >> 2, warpN = wid & 3;

  float acc[4][4][4];
  #pragma unroll
  for (int i = 0; i < 4; i++)
    #pragma unroll
    for (int j = 0; j < 4; j++)
      #pragma unroll
      for (int c = 0; c < 4; c++) acc[i][j][c] = 0.f;

  const float* Bb = g_f1o + (size_t)b*256*HW + pb;

  for (int kc = 0; kc < 8; kc++) {
    const int k0 = kc * 32;
    #pragma unroll
    for (int it = 0; it < 4; it++) {
      int s = tid + it*256;
      int m = s >> 3, kb = (s & 7) * 4;
      float4 f = make_float4(0.f,0.f,0.f,0.f);
      if (mb + m < 1176) f = *(const float4*)(A + (size_t)(mb+m)*256 + k0 + kb);
      float4 o; o.x = tf32f(f.x); o.y = tf32f(f.y); o.z = tf32f(f.z); o.w = tf32f(f.w);
      *(float4*)&As[m][kb] = o;
    }
    #pragma unroll
    for (int it = 0; it < 4; it++) {
      int s = tid + it*256;
      int k = s >> 5, nb = (s & 31) * 4;
      float4 f = *(const float4*)(Bb + (size_t)(k0+k)*HW + nb);
      float4 o; o.x = tf32f(f.x); o.y = tf32f(f.y); o.z = tf32f(f.z); o.w = tf32f(f.w);
      *(float4*)&Bs[k][nb] = o;
    }
    __syncthreads();
    #pragma unroll
    for (int s = 0; s < 4; s++) {
      const int ka = s*8 + (lane & 3);
      const int mrow = warpM*64 + (lane >> 2);
      const int ncol = warpN*32 + (lane >> 2);
      uint32_t a[4][4], bf[4][2];
      #pragma unroll
      for (int mt = 0; mt < 4; mt++) {
        a[mt][0] = __float_as_uint(As[mrow + mt*16    ][ka]);
        a[mt][1] = __float_as_uint(As[mrow + mt*16 + 8][ka]);
        a[mt][2] = __float_as_uint(As[mrow + mt*16    ][ka+4]);
        a[mt][3] = __float_as_uint(As[mrow + mt*16 + 8][ka+4]);
      }
      #pragma unroll
      for (int nt = 0; nt < 4; nt++) {
        bf[nt][0] = __float_as_uint(Bs[ka  ][ncol + nt*8]);
        bf[nt][1] = __float_as_uint(Bs[ka+4][ncol + nt*8]);
      }
      #pragma unroll
      for (int mt = 0; mt < 4; mt++)
        #pragma unroll
        for (int nt = 0; nt < 4; nt++)
          mma_tf32(acc[mt][nt], a[mt], bf[nt]);
    }
    __syncthreads();
  }
  #pragma unroll
  for (int mt = 0; mt < 4; mt++) {
    int m0 = mb + warpM*64 + mt*16 + (lane >> 2);
    int m1 = m0 + 8;
    float bv0 = (m0 < 1176) ? bias[m0] : 0.f;
    float bv1 = (m1 < 1176) ? bias[m1] : 0.f;
    float* r0 = g_wbuf + ((size_t)b*1176 + m0)*HW + pb;
    float* r1 = g_wbuf + ((size_t)b*1176 + m1)*HW + pb;
    #pragma unroll
    for (int nt = 0; nt < 4; nt++) {
      int p = warpN*32 + nt*8 + (lane & 3)*2;
      if (m0 < 1176) { float2 v; v.x = acc[mt][nt][0]+bv0; v.y = acc[mt][nt][1]+bv0; *(float2*)(r0+p) = v; }
      if (m1 < 1176) { float2 v; v.x = acc[mt][nt][2]+bv1; v.y = acc[mt][nt][3]+bv1; *(float2*)(r1+p) = v; }
    }
  }
}

// ------------------- intensity scale + softmax over 49 taps -> u16 fixed point --------------
__global__ __launch_bounds__(256) void softmax_kernel() {
  size_t idx = (size_t)blockIdx.x*256 + threadIdx.x;
  int p = (int)(idx & 16383);
  int bc = (int)(idx >> 14);
  int b = bc / 24;
  float im = g_intens[(size_t)b*HW + p];
  const float* wp = g_wbuf + ((size_t)bc*49)*HW + p;
  unsigned short* wq = g_wq + ((size_t)bc*49)*HW + p;
  float v[49]; float mx = -1e30f;
  #pragma unroll
  for (int t = 0; t < 49; t++) { v[t] = wp[(size_t)t*HW]*im; mx = fmaxf(mx, v[t]); }
  float s = 0.f;
  #pragma unroll
  for (int t = 0; t < 49; t++) { v[t] = expf(v[t]-mx); s += v[t]; }
  float inv = 65535.f/s;
  #pragma unroll
  for (int t = 0; t < 49; t++)
    wq[(size_t)t*HW] = (unsigned short)__float2uint_rn(v[t]*inv);
}

// ------------------------- one diffusion step (u16 weights) --------------
__global__ __launch_bounds__(256) void diffusion_kernel(const float* __restrict__ lat,
    float* __restrict__ out) {
  int tx = threadIdx.x & 31, ty = threadIdx.x >> 5;
  int x0 = blockIdx.x*32, y0 = blockIdx.y*8;
  int bc = blockIdx.z;
  __shared__ float sm[14][40];
  const float* lp = lat + (size_t)bc*HW;
  for (int i = threadIdx.x; i < 14*38; i += 256) {
    int r = i/38, c = i - r*38;
    int gy = min(max(y0 + r - 3, 0), 127);
    int gx = min(max(x0 + c - 3, 0), 127);
    sm[r][c] = lp[gy*128+gx];
  }
  __syncthreads();
  int x = x0+tx, y = y0+ty;
  const unsigned short* wp = g_wq + ((size_t)bc*49)*HW + y*128 + x;
  float acc = 0.f;
  #pragma unroll
  for (int t = 0; t < 49; t++) {
    int di = t/7, dj = t - di*7;
    acc += (float)wp[(size_t)t*HW] * sm[ty+di][tx+dj];
  }
  out[(size_t)bc*HW + y*128 + x] = acc * (1.f/65535.f);
}

// ------------------------- launch -------------------------
extern "C" void kernel_launch(void* const* d_in, const int* in_sizes, int n_in,
                              void* d_out, int out_size) {
  const float* depth  = (const float*)d_in[0];
  const float* texf   = (const float*)d_in[1];
  const int*   labels = (const int*)d_in[2];
  const float* w_te1  = (const float*)d_in[3];
  const float* b_te1  = (const float*)d_in[4];
  const float* w_te2  = (const float*)d_in[5];
  const float* b_te2  = (const float*)d_in[6];
  const float* emb    = (const float*)d_in[7];
  const float* w_f1   = (const float*)d_in[8];
  const float* b_f1   = (const float*)d_in[9];
  const float* w_f2   = (const float*)d_in[10];
  const float* b_f2   = (const float*)d_in[11];
  const float* w_g1   = (const float*)d_in[12];
  const float* b_g1   = (const float*)d_in[13];
  const float* w_g2   = (const float*)d_in[14];
  const float* b_g2   = (const float*)d_in[15];
  const float* ci     = (const float*)d_in[16];
  float* out = (float*)d_out;

  float *t1, *tex, *g1b, *latA, *latB, *f1o, *wt, *wt2, *wtg;
  cudaGetSymbolAddress((void**)&t1,  g_t1);
  cudaGetSymbolAddress((void**)&tex, g_tex);
  cudaGetSymbolAddress((void**)&g1b, g_g1b);
  cudaGetSymbolAddress((void**)&latA, g_latA);
  cudaGetSymbolAddress((void**)&latB, g_latB);
  cudaGetSymbolAddress((void**)&f1o, g_f1o);
  cudaGetSymbolAddress((void**)&wt,  g_wt);
  cudaGetSymbolAddress((void**)&wt2, g_wt2);
  cudaGetSymbolAddress((void**)&wtg, g_wtg);

  const int SMEM128 = (3*32*136 + 32*136)*4;   // 69632
  const int SMEM64  = (3*32*72  + 32*136)*4;   // 45056
  static bool attr_set = false;
  if (!attr_set) {
    cudaFuncSetAttribute(conv_mma_kernel<128,128,true>,  cudaFuncAttributeMaxDynamicSharedMemorySize, SMEM128);
    cudaFuncSetAttribute(conv_mma_kernel<64,128,false>,  cudaFuncAttributeMaxDynamicSharedMemorySize, SMEM128);
    cudaFuncSetAttribute(conv_mma_kernel<128,64,false>,  cudaFuncAttributeMaxDynamicSharedMemorySize, SMEM64);
    attr_set = true;
  }

  // weight prep (tf32 transposes) + emb tap sums
  wtrans_kernel<<<(9*64*128+255)/256,  256>>>(w_te2, wt2, 64, 128, 576, 9*64*128);
  wtrans_kernel<<<(9*128*64+255)/256,  256>>>(w_g1,  wtg, 128, 64, 1152, 9*128*64);
  wtrans_kernel<<<(9*128*256+255)/256, 256>>>(w_f1,  wt,  128, 256, 2304, 9*128*256);
  embS_kernel<<<36, 256>>>(w_f1, emb, labels);

  // texture encoder
  te1_kernel<<<dim3(128,4), 128>>>(texf, w_te1, b_te1);
  conv_mma_kernel<64,128,false><<<dim3(128,1,4), 256, SMEM128>>>(wt2, b_te2, t1, tex, 128);
  // gate path
  conv_mma_kernel<128,64,false><<<dim3(128,1,4), 256, SMEM64>>>(wtg, b_g1, tex, g1b, 64);
  gate_kernel<<<dim3(64,4), 256>>>(w_g2, b_g2, labels, ci,
                                   out + (size_t)4*24*HW,
                                   out + (size_t)4*24*HW + (size_t)4*6*HW);
  // fusion path
  conv_mma_kernel<128,128,true><<<dim3(128,2,4), 256, SMEM128>>>(wt, b_f1, tex, f1o, 256);
  f2_mma_kernel<<<dim3(128,10,4), 256>>>(w_f2, b_f2);
  softmax_kernel<<<6144, 256>>>();

  // 8 diffusion steps (ping-pong), final into d_out
  diffusion_kernel<<<dim3(4,16,96), 256>>>(depth, latA);
  diffusion_kernel<<<dim3(4,16,96), 256>>>(latA, latB);
  diffusion_kernel<<<dim3(4,16,96), 256>>>(latB, latA);
  diffusion_kernel<<<dim3(4,16,96), 256>>>(latA, latB);
  diffusion_kernel<<<dim3(4,16,96), 256>>>(latB, latA);
  diffusion_kernel<<<dim3(4,16,96), 256>>>(latA, latB);
  diffusion_kernel<<<dim3(4,16,96), 256>>>(latB, latA);
  diffusion_kernel<<<dim3(4,16,96), 256>>>(latA, out);
}